// round 1
// baseline (speedup 1.0000x reference)
#include <cuda_runtime.h>
#include <math.h>

// Problem constants
#define Bsz 512
#define Tn  256
#define Dn  81
#define Hn  128
#define Gn  512            // 4*H
#define RPB 4              // batch rows per block
#define NTHREADS 256
#define NBLOCKS (Bsz / RPB)

// Shared memory layout (float offsets). All arrays 16B-aligned.
#define DPAD 84            // D padded to mult of 4
#define W2PAD 132          // W2 row stride (conflict-free, 16B aligned)
#define OFF_WIH   0                         // [512][81]
#define OFF_W2    (OFF_WIH + Gn*Dn)         // [81][132]
#define OFF_H     (OFF_W2 + Dn*W2PAD)       // [4][128]
#define OFF_C     (OFF_H + RPB*Hn)          // [4][128]
#define OFF_A1    (OFF_C + RPB*Hn)          // [4][128]
#define OFF_GATES (OFF_A1 + RPB*Hn)         // [4][512]
#define OFF_XW    (OFF_GATES + RPB*Gn)      // [4][84]
#define OFF_BIAS  (OFF_XW + RPB*DPAD)       // [512]  (b_ih + b_hh)
#define OFF_B1    (OFF_BIAS + Gn)           // [128]
#define OFF_B2    (OFF_B1 + Hn)             // [84]
#define OFF_E     (OFF_B2 + DPAD)           // [4][84]
#define SMEM_FLOATS (OFF_E + RPB*DPAD)

__device__ __forceinline__ float sigmoidf_(float x) {
    return 1.0f / (1.0f + expf(-x));
}

__global__ __launch_bounds__(NTHREADS, 1)
void encoder_kernel(const float* __restrict__ X,
                    const float* __restrict__ W1,
                    const float* __restrict__ b1,
                    const float* __restrict__ W2,
                    const float* __restrict__ b2,
                    const float* __restrict__ Wih,
                    const float* __restrict__ Whh,
                    const float* __restrict__ bih,
                    const float* __restrict__ bhh,
                    float* __restrict__ outH,
                    float* __restrict__ outA)
{
    extern __shared__ float sm[];
    float* sWih  = sm + OFF_WIH;
    float* sW2   = sm + OFF_W2;
    float* sh    = sm + OFF_H;
    float* sc    = sm + OFF_C;
    float* sa1   = sm + OFF_A1;
    float* sgate = sm + OFF_GATES;
    float* sxw   = sm + OFF_XW;
    float* sbias = sm + OFF_BIAS;
    float* sb1   = sm + OFF_B1;
    float* sb2   = sm + OFF_B2;
    float* se    = sm + OFF_E;

    const int tid = threadIdx.x;
    const int b0  = blockIdx.x * RPB;

    // ---- One-time loads into SMEM ----
    for (int i = tid; i < Gn * Dn; i += NTHREADS) sWih[i] = Wih[i];
    for (int i = tid; i < Dn * Hn; i += NTHREADS) {
        int o = i >> 7, k = i & (Hn - 1);
        sW2[o * W2PAD + k] = W2[i];
    }
    for (int i = tid; i < Gn; i += NTHREADS) sbias[i] = bih[i] + bhh[i];
    if (tid < Hn) sb1[tid] = b1[tid];
    if (tid < Dn) sb2[tid] = b2[tid];
    for (int i = tid; i < RPB * Hn; i += NTHREADS) { sh[i] = 0.0f; sc[i] = 0.0f; }
    __syncthreads();

    // Phase-A mapping: thread -> (W1 output row j, row-pair rh)
    const int j  = tid & (Hn - 1);
    const int rh = tid >> 7;                 // 0 -> rows 0,1 ; 1 -> rows 2,3
    const float* w1row = W1 + (size_t)j * (2 * Hn);

    // Phase-D mapping: gate outputs j0 = tid, j1 = tid + 256
    const int j0 = tid;
    const int j1 = tid + NTHREADS;
    const float* wi0 = sWih + j0 * Dn;
    const float* wi1 = sWih + j1 * Dn;
    const float* wh0 = Whh + (size_t)j0 * Hn;
    const float* wh1 = Whh + (size_t)j1 * Hn;

    for (int t = 0; t < Tn; ++t) {
        // ================= Phase A: a1 = tanh(W1 @ [h;c] + b1) =================
        {
            float acc0 = sb1[j];
            float acc1 = acc0;
            const int r0 = 2 * rh, r1 = 2 * rh + 1;
            const float* p0 = sh + r0 * Hn;
            const float* p1 = sh + r1 * Hn;
            #pragma unroll 4
            for (int k = 0; k < Hn; k += 4) {
                float4 w = *(const float4*)(w1row + k);
                float4 u = *(const float4*)(p0 + k);
                float4 v = *(const float4*)(p1 + k);
                acc0 = fmaf(w.x, u.x, fmaf(w.y, u.y, fmaf(w.z, u.z, fmaf(w.w, u.w, acc0))));
                acc1 = fmaf(w.x, v.x, fmaf(w.y, v.y, fmaf(w.z, v.z, fmaf(w.w, v.w, acc1))));
            }
            const float* q0 = sc + r0 * Hn;
            const float* q1 = sc + r1 * Hn;
            const float* w1c = w1row + Hn;
            #pragma unroll 4
            for (int k = 0; k < Hn; k += 4) {
                float4 w = *(const float4*)(w1c + k);
                float4 u = *(const float4*)(q0 + k);
                float4 v = *(const float4*)(q1 + k);
                acc0 = fmaf(w.x, u.x, fmaf(w.y, u.y, fmaf(w.z, u.z, fmaf(w.w, u.w, acc0))));
                acc1 = fmaf(w.x, v.x, fmaf(w.y, v.y, fmaf(w.z, v.z, fmaf(w.w, v.w, acc1))));
            }
            sa1[r0 * Hn + j] = tanhf(acc0);
            sa1[r1 * Hn + j] = tanhf(acc1);
        }
        __syncthreads();

        // ================= Phase B: e = W2 @ a1 + b2 =================
        for (int idx = tid; idx < RPB * Dn; idx += NTHREADS) {
            int r = idx / Dn;
            int o = idx - r * Dn;
            const float* w2row = sW2 + o * W2PAD;
            const float* a1r   = sa1 + r * Hn;
            float acc = sb2[o];
            #pragma unroll 8
            for (int k = 0; k < Hn; k += 4) {
                float4 w = *(const float4*)(w2row + k);
                float4 a = *(const float4*)(a1r + k);
                acc = fmaf(w.x, a.x, fmaf(w.y, a.y, fmaf(w.z, a.z, fmaf(w.w, a.w, acc))));
            }
            se[r * DPAD + o] = acc;
        }
        __syncthreads();

        // ===== Phase C: softmax over D per row; alpha out; xw = alpha * x_t =====
        if (tid < 4 * 32) {
            const int r = tid >> 5;
            const int lane = tid & 31;
            float* er = se + r * DPAD;
            float v0 = er[lane];
            float v1 = er[lane + 32];
            float v2 = (lane < Dn - 64) ? er[lane + 64] : -3.4e38f;
            float m = fmaxf(fmaxf(v0, v1), v2);
            #pragma unroll
            for (int s = 16; s; s >>= 1) m = fmaxf(m, __shfl_xor_sync(0xffffffffu, m, s));
            float e0 = expf(v0 - m);
            float e1 = expf(v1 - m);
            float e2 = (lane < Dn - 64) ? expf(v2 - m) : 0.0f;
            float ssum = e0 + e1 + e2;
            #pragma unroll
            for (int s = 16; s; s >>= 1) ssum += __shfl_xor_sync(0xffffffffu, ssum, s);
            const float inv = 1.0f / ssum;

            const float* xrow = X + ((size_t)(b0 + r) * Tn + t) * Dn;
            float* xwr  = sxw + r * DPAD;
            float* arow = outA + ((size_t)(b0 + r) * Tn + t) * Dn;

            float a0 = e0 * inv;
            arow[lane] = a0;          xwr[lane]      = a0 * xrow[lane];
            float a1v = e1 * inv;
            arow[lane + 32] = a1v;    xwr[lane + 32] = a1v * xrow[lane + 32];
            if (lane < Dn - 64) {
                float a2 = e2 * inv;
                arow[lane + 64] = a2; xwr[lane + 64] = a2 * xrow[lane + 64];
            }
        }
        __syncthreads();

        // ===== Phase D: gates = W_ih @ xw + W_hh @ h + (b_ih + b_hh) =====
        {
            float acc[RPB][2];
            #pragma unroll
            for (int r = 0; r < RPB; ++r) {
                acc[r][0] = sbias[j0];
                acc[r][1] = sbias[j1];
            }
            // K over D = 81 (SMEM-resident W_ih)
            for (int k = 0; k < Dn; ++k) {
                float w0 = wi0[k];
                float w1v = wi1[k];
                #pragma unroll
                for (int r = 0; r < RPB; ++r) {
                    float x = sxw[r * DPAD + k];
                    acc[r][0] = fmaf(w0, x, acc[r][0]);
                    acc[r][1] = fmaf(w1v, x, acc[r][1]);
                }
            }
            // K over H = 128 (W_hh streamed from L2)
            #pragma unroll 4
            for (int k = 0; k < Hn; k += 4) {
                float4 w0 = *(const float4*)(wh0 + k);
                float4 w1v = *(const float4*)(wh1 + k);
                #pragma unroll
                for (int r = 0; r < RPB; ++r) {
                    float4 h4 = *(const float4*)(sh + r * Hn + k);
                    acc[r][0] = fmaf(w0.x, h4.x, fmaf(w0.y, h4.y,
                                 fmaf(w0.z, h4.z, fmaf(w0.w, h4.w, acc[r][0]))));
                    acc[r][1] = fmaf(w1v.x, h4.x, fmaf(w1v.y, h4.y,
                                 fmaf(w1v.z, h4.z, fmaf(w1v.w, h4.w, acc[r][1]))));
                }
            }
            #pragma unroll
            for (int r = 0; r < RPB; ++r) {
                sgate[r * Gn + j0] = acc[r][0];
                sgate[r * Gn + j1] = acc[r][1];
            }
        }
        __syncthreads();

        // ===== Phase E: LSTM cell update, write h out =====
        if (tid < Hn) {
            #pragma unroll
            for (int r = 0; r < RPB; ++r) {
                float gi = sgate[r * Gn + tid];
                float gf = sgate[r * Gn + Hn + tid];
                float gg = sgate[r * Gn + 2 * Hn + tid];
                float go = sgate[r * Gn + 3 * Hn + tid];
                float si = sigmoidf_(gi);
                float sf = sigmoidf_(gf);
                float so = sigmoidf_(go);
                float cn = sf * sc[r * Hn + tid] + si * tanhf(gg);
                float hn = so * tanhf(cn);
                sc[r * Hn + tid] = cn;
                sh[r * Hn + tid] = hn;
                outH[((size_t)(b0 + r) * Tn + t) * Hn + tid] = hn;
            }
        }
        __syncthreads();
    }
}

extern "C" void kernel_launch(void* const* d_in, const int* in_sizes, int n_in,
                              void* d_out, int out_size)
{
    const float* X    = (const float*)d_in[0];
    const float* W1   = (const float*)d_in[1];
    const float* b1   = (const float*)d_in[2];
    const float* W2   = (const float*)d_in[3];
    const float* b2   = (const float*)d_in[4];
    const float* Wih  = (const float*)d_in[5];
    const float* Whh  = (const float*)d_in[6];
    const float* bih  = (const float*)d_in[7];
    const float* bhh  = (const float*)d_in[8];

    float* outH = (float*)d_out;                          // [B, T, H]
    float* outA = outH + (size_t)Bsz * Tn * Hn;           // [B, T, D]

    const size_t smem_bytes = (size_t)SMEM_FLOATS * sizeof(float);
    cudaFuncSetAttribute(encoder_kernel,
                         cudaFuncAttributeMaxDynamicSharedMemorySize,
                         (int)smem_bytes);

    encoder_kernel<<<NBLOCKS, NTHREADS, smem_bytes>>>(
        X, W1, b1, W2, b2, Wih, Whh, bih, bhh, outH, outA);
}

// round 2
// speedup vs baseline: 1.4971x; 1.4971x over previous
#include <cuda_runtime.h>
#include <math.h>

// Problem constants
#define Bsz 512
#define Tn  256
#define Dn  81
#define Hn  128
#define Gn  512            // 4*H
#define RPB 4              // batch rows per block
#define NTH 512            // threads per block (16 warps)
#define NWARP 16
#define NBLK (Bsz / RPB)   // 128 blocks
#define DPAD 84            // D padded to multiple of 4 (84*4B = 336B, 16B aligned)

// Shared memory layout (float offsets)
#define OFF_WIH   0                          // [512][84]  (cols 81..83 zero)
#define OFF_BIAS  (OFF_WIH + Gn*DPAD)        // [512] b_ih + b_hh
#define OFF_B1    (OFF_BIAS + Gn)            // [128]
#define OFF_B2    (OFF_B1 + Hn)              // [84]
#define OFF_H     (OFF_B2 + DPAD)            // [4][128]
#define OFF_C     (OFF_H + RPB*Hn)           // [4][128]
#define OFF_A1    (OFF_C + RPB*Hn)           // [4][128]
#define OFF_G     (OFF_A1 + RPB*Hn)          // [4][512]
#define OFF_XW    (OFF_G + RPB*Gn)           // [4][84]  (cols 81..83 zero)
#define OFF_E     (OFF_XW + RPB*DPAD)        // [4][84]
#define SMEM_FLOATS (OFF_E + RPB*DPAD)

__device__ __forceinline__ float sigmoidf_(float x) {
    return 1.0f / (1.0f + expf(-x));
}

__device__ __forceinline__ float dot4(float4 w, float4 v, float acc) {
    return fmaf(w.x, v.x, fmaf(w.y, v.y, fmaf(w.z, v.z, fmaf(w.w, v.w, acc))));
}

__device__ __forceinline__ float warp_reduce_kc(float acc) {
    // sum over the 8 kc-lanes within each r-group (xor on lane bits 0..2)
    acc += __shfl_xor_sync(0xffffffffu, acc, 1);
    acc += __shfl_xor_sync(0xffffffffu, acc, 2);
    acc += __shfl_xor_sync(0xffffffffu, acc, 4);
    return acc;
}

__global__ __launch_bounds__(NTH, 1)
void encoder_kernel(const float* __restrict__ X,
                    const float* __restrict__ W1,
                    const float* __restrict__ b1,
                    const float* __restrict__ W2,
                    const float* __restrict__ b2,
                    const float* __restrict__ Wih,
                    const float* __restrict__ Whh,
                    const float* __restrict__ bih,
                    const float* __restrict__ bhh,
                    float* __restrict__ outH,
                    float* __restrict__ outA)
{
    extern __shared__ float sm[];
    float* sWih  = sm + OFF_WIH;
    float* sbias = sm + OFF_BIAS;
    float* sb1   = sm + OFF_B1;
    float* sb2   = sm + OFF_B2;
    float* sh    = sm + OFF_H;
    float* sc    = sm + OFF_C;
    float* sa1   = sm + OFF_A1;
    float* sgate = sm + OFF_G;
    float* sxw   = sm + OFF_XW;
    float* se    = sm + OFF_E;

    const int tid  = threadIdx.x;
    const int wid  = tid >> 5;
    const int lane = tid & 31;
    const int r    = lane >> 3;   // batch row within block (0..3)
    const int kc   = lane & 7;    // K-chunk lane (0..7)
    const int b0   = blockIdx.x * RPB;

    // ---- One-time loads into SMEM ----
    for (int i = tid; i < Gn * DPAD; i += NTH) {
        int row = i / DPAD, col = i - row * DPAD;
        sWih[i] = (col < Dn) ? Wih[row * Dn + col] : 0.0f;
    }
    for (int i = tid; i < Gn; i += NTH) sbias[i] = bih[i] + bhh[i];
    if (tid < Hn)   sb1[tid] = b1[tid];
    if (tid < DPAD) sb2[tid] = (tid < Dn) ? b2[tid] : 0.0f;
    for (int i = tid; i < RPB * Hn; i += NTH) { sh[i] = 0.0f; sc[i] = 0.0f; }
    __syncthreads();

    for (int t = 0; t < Tn; ++t) {
        // ========= Phase A: a1 = tanh(W1 @ [h;c] + b1), 8 outputs/warp =========
        {
            // register slice of [h;c]: hcA[m] = hc[r][m*32 + kc*4 .. +3]
            float4 hcA[8];
            #pragma unroll
            for (int m = 0; m < 8; ++m) {
                const float* src = (m < 4) ? (sh + r * Hn + m * 32)
                                           : (sc + r * Hn + (m - 4) * 32);
                hcA[m] = *(const float4*)(src + kc * 4);
            }
            #pragma unroll 2
            for (int oi = 0; oi < 8; ++oi) {
                const int j = wid * 8 + oi;
                const float4* w = (const float4*)(W1 + (size_t)j * (2 * Hn));
                float acc = 0.0f;
                #pragma unroll
                for (int m = 0; m < 8; ++m) {
                    float4 wv = __ldg(w + m * 8 + kc);   // 128B-consecutive per inst
                    acc = dot4(wv, hcA[m], acc);
                }
                acc = warp_reduce_kc(acc);
                if (kc == 0) sa1[r * Hn + j] = tanhf(acc + sb1[j]);
            }
        }
        __syncthreads();

        // ========= Phase B: e = W2 @ a1 + b2, up to 6 outputs/warp =========
        {
            float4 aA[4];
            #pragma unroll
            for (int i = 0; i < 4; ++i)
                aA[i] = *(const float4*)(sa1 + r * Hn + i * 32 + kc * 4);
            #pragma unroll
            for (int oi = 0; oi < 6; ++oi) {
                const int j = wid * 6 + oi;
                if (j < Dn) {
                    const float4* w = (const float4*)(W2 + (size_t)j * Hn);
                    float acc = 0.0f;
                    #pragma unroll
                    for (int i = 0; i < 4; ++i) {
                        float4 wv = __ldg(w + i * 8 + kc);
                        acc = dot4(wv, aA[i], acc);
                    }
                    acc = warp_reduce_kc(acc);
                    if (kc == 0) se[r * DPAD + j] = acc + sb2[j];
                }
            }
        }
        __syncthreads();

        // ===== Phase C: softmax over D; write alpha; xw = alpha * x_t =====
        if (tid < 4 * 32) {
            const int cr = tid >> 5;
            const int cl = tid & 31;
            float* er = se + cr * DPAD;
            float v0 = er[cl];
            float v1 = er[cl + 32];
            float v2 = (cl < Dn - 64) ? er[cl + 64] : -3.4e38f;
            float m = fmaxf(fmaxf(v0, v1), v2);
            #pragma unroll
            for (int s = 16; s; s >>= 1) m = fmaxf(m, __shfl_xor_sync(0xffffffffu, m, s));
            float e0 = expf(v0 - m);
            float e1 = expf(v1 - m);
            float e2 = (cl < Dn - 64) ? expf(v2 - m) : 0.0f;
            float ssum = e0 + e1 + e2;
            #pragma unroll
            for (int s = 16; s; s >>= 1) ssum += __shfl_xor_sync(0xffffffffu, ssum, s);
            const float inv = 1.0f / ssum;

            const float* xrow = X + ((size_t)(b0 + cr) * Tn + t) * Dn;
            float* xwr  = sxw + cr * DPAD;
            float* arow = outA + ((size_t)(b0 + cr) * Tn + t) * Dn;

            float a0 = e0 * inv;
            arow[cl] = a0;          xwr[cl]      = a0 * xrow[cl];
            float a1v = e1 * inv;
            arow[cl + 32] = a1v;    xwr[cl + 32] = a1v * xrow[cl + 32];
            if (cl < Dn - 64) {
                float a2 = e2 * inv;
                arow[cl + 64] = a2; xwr[cl + 64] = a2 * xrow[cl + 64];
            }
            if (cl < DPAD - Dn) xwr[Dn + cl] = 0.0f;   // zero padding cols 81..83
        }
        __syncthreads();

        // ===== Phase D: gates = W_ih @ xw + W_hh @ h + bias, 32 outputs/warp =====
        {
            float4 hD[4];
            #pragma unroll
            for (int i = 0; i < 4; ++i)
                hD[i] = *(const float4*)(sh + r * Hn + i * 32 + kc * 4);
            float4 xwD[3];
            xwD[0] = *(const float4*)(sxw + r * DPAD + 0 * 32 + kc * 4);
            xwD[1] = *(const float4*)(sxw + r * DPAD + 1 * 32 + kc * 4);
            if (kc < 5) {
                xwD[2] = *(const float4*)(sxw + r * DPAD + 2 * 32 + kc * 4);
            } else {
                xwD[2] = make_float4(0.0f, 0.0f, 0.0f, 0.0f);
            }

            #pragma unroll 4
            for (int oi = 0; oi < 32; ++oi) {
                const int j = wid * 32 + oi;
                const float4* wh = (const float4*)(Whh + (size_t)j * Hn);
                float acc = 0.0f;
                #pragma unroll
                for (int i = 0; i < 4; ++i) {
                    float4 wv = __ldg(wh + i * 8 + kc);
                    acc = dot4(wv, hD[i], acc);
                }
                const float4* wi = (const float4*)(sWih + j * DPAD);
                #pragma unroll
                for (int i = 0; i < 3; ++i) {
                    // i=2, kc>=5 reads stray floats but xwD[2] is zero there
                    float4 wv = wi[i * 8 + kc];
                    acc = dot4(wv, xwD[i], acc);
                }
                acc = warp_reduce_kc(acc);
                if (kc == 0) sgate[r * Gn + j] = acc + sbias[j];
            }
        }
        __syncthreads();

        // ===== Phase E: LSTM cell update, write h out =====
        if (tid < Hn) {
            #pragma unroll
            for (int rr = 0; rr < RPB; ++rr) {
                float gi = sgate[rr * Gn + tid];
                float gf = sgate[rr * Gn + Hn + tid];
                float gg = sgate[rr * Gn + 2 * Hn + tid];
                float go = sgate[rr * Gn + 3 * Hn + tid];
                float si = sigmoidf_(gi);
                float sf = sigmoidf_(gf);
                float so = sigmoidf_(go);
                float cn = sf * sc[rr * Hn + tid] + si * tanhf(gg);
                float hn = so * tanhf(cn);
                sc[rr * Hn + tid] = cn;
                sh[rr * Hn + tid] = hn;
                outH[((size_t)(b0 + rr) * Tn + t) * Hn + tid] = hn;
            }
        }
        __syncthreads();
    }
}

extern "C" void kernel_launch(void* const* d_in, const int* in_sizes, int n_in,
                              void* d_out, int out_size)
{
    const float* X    = (const float*)d_in[0];
    const float* W1   = (const float*)d_in[1];
    const float* b1   = (const float*)d_in[2];
    const float* W2   = (const float*)d_in[3];
    const float* b2   = (const float*)d_in[4];
    const float* Wih  = (const float*)d_in[5];
    const float* Whh  = (const float*)d_in[6];
    const float* bih  = (const float*)d_in[7];
    const float* bhh  = (const float*)d_in[8];

    float* outH = (float*)d_out;                          // [B, T, H]
    float* outA = outH + (size_t)Bsz * Tn * Hn;           // [B, T, D]

    const size_t smem_bytes = (size_t)SMEM_FLOATS * sizeof(float);
    cudaFuncSetAttribute(encoder_kernel,
                         cudaFuncAttributeMaxDynamicSharedMemorySize,
                         (int)smem_bytes);

    encoder_kernel<<<NBLK, NTH, smem_bytes>>>(
        X, W1, b1, W2, b2, Wih, Whh, bih, bhh, outH, outA);
}

// round 4
// speedup vs baseline: 1.6375x; 1.0938x over previous
#include <cuda_runtime.h>
#include <math.h>

// Problem constants
#define Bsz 512
#define Tn  256
#define Dn  81
#define Hn  128
#define Gn  512            // 4*H
#define RPB 4              // batch rows per block
#define NTH 1024           // threads per block (32 warps)
#define NBLK (Bsz / RPB)   // 128 blocks
#define DPAD 84            // D padded to multiple of 4

// Shared memory layout (float offsets)
#define OFF_WIH   0                          // [512][84] (cols 81..83 zero)
#define OFF_BIAS  (OFF_WIH + Gn*DPAD)        // [512] b_ih + b_hh
#define OFF_B1    (OFF_BIAS + Gn)            // [128]
#define OFF_B2    (OFF_B1 + Hn)              // [84]
#define OFF_H     (OFF_B2 + DPAD)            // [4][128]
#define OFF_C     (OFF_H + RPB*Hn)           // [4][128]
#define OFF_A1    (OFF_C + RPB*Hn)           // [4][128]
#define OFF_G     (OFF_A1 + RPB*Hn)          // [4][512]
#define OFF_XW    (OFF_G + RPB*Gn)           // [4][84] (cols 81..83 zero)
#define OFF_E     (OFF_XW + RPB*DPAD)        // [4][84]
#define SMEM_FLOATS (OFF_E + RPB*DPAD)

__device__ __forceinline__ float sigmoidf_(float x) {
    return 1.0f / (1.0f + expf(-x));
}

__device__ __forceinline__ float dot4(float4 w, float4 v, float acc) {
    return fmaf(w.x, v.x, fmaf(w.y, v.y, fmaf(w.z, v.z, fmaf(w.w, v.w, acc))));
}

// Butterfly multi-reduce: 4 partial sums (one per output) held by each of the
// 8 kc-lanes of an r-group -> each lane ends with ONE fully-reduced output.
// Output index mapping: o = 2*(kc&1) | ((kc&2)?1:0). Lanes kc and kc^4 hold
// duplicates; only kc<4 stores. 4 shfls total (vs 12 for per-output reduce).
__device__ __forceinline__ void reduce4(const float p[4], int kc, float& d, int& o) {
    const bool b0 = (kc & 1);
    float q0 = b0 ? p[0] : p[2];
    float q1 = b0 ? p[1] : p[3];
    float v0 = __shfl_xor_sync(0xffffffffu, q0, 1);
    float v1 = __shfl_xor_sync(0xffffffffu, q1, 1);
    float a0 = (b0 ? p[2] : p[0]) + v0;
    float a1 = (b0 ? p[3] : p[1]) + v1;
    const bool b1 = (kc & 2);
    float q = b1 ? a0 : a1;
    float v = __shfl_xor_sync(0xffffffffu, q, 2);
    d = (b1 ? a1 : a0) + v;
    d += __shfl_xor_sync(0xffffffffu, d, 4);
    o = (b0 ? 2 : 0) | (b1 ? 1 : 0);
}

__global__ __launch_bounds__(NTH, 1)
void encoder_kernel(const float* __restrict__ X,
                    const float* __restrict__ W1,
                    const float* __restrict__ b1,
                    const float* __restrict__ W2,
                    const float* __restrict__ b2,
                    const float* __restrict__ Wih,
                    const float* __restrict__ Whh,
                    const float* __restrict__ bih,
                    const float* __restrict__ bhh,
                    float* __restrict__ outH,
                    float* __restrict__ outA)
{
    extern __shared__ float sm[];
    float* sWih  = sm + OFF_WIH;
    float* sbias = sm + OFF_BIAS;
    float* sb1   = sm + OFF_B1;
    float* sb2   = sm + OFF_B2;
    float* sh    = sm + OFF_H;
    float* sc    = sm + OFF_C;
    float* sa1   = sm + OFF_A1;
    float* sgate = sm + OFF_G;
    float* sxw   = sm + OFF_XW;
    float* se    = sm + OFF_E;

    const int tid  = threadIdx.x;
    const int wid  = tid >> 5;          // 0..31
    const int lane = tid & 31;
    const int r    = lane >> 3;         // batch row 0..3
    const int kc   = lane & 7;          // K-chunk lane 0..7
    const int b0i  = blockIdx.x * RPB;

    // ---- One-time loads into SMEM ----
    for (int i = tid; i < Gn * DPAD; i += NTH) {
        int row = i / DPAD, col = i - row * DPAD;
        sWih[i] = (col < Dn) ? Wih[row * Dn + col] : 0.0f;
    }
    for (int i = tid; i < Gn; i += NTH) sbias[i] = bih[i] + bhh[i];
    if (tid < Hn)   sb1[tid] = b1[tid];
    if (tid < DPAD) sb2[tid] = (tid < Dn) ? b2[tid] : 0.0f;
    for (int i = tid; i < RPB * Hn; i += NTH) { sh[i] = 0.0f; sc[i] = 0.0f; }
    __syncthreads();

    for (int t = 0; t < Tn; ++t) {
        // ===== Phase A: a1 = tanh(W1 @ [h;c] + b1); 4 outputs/warp =====
        {
            const int jb = wid * 4;                    // 32 warps * 4 = 128 outputs
            float p[4] = {0.f, 0.f, 0.f, 0.f};
            float4 act[4];
            // pass 1: h part (W1 cols 0..127)
            #pragma unroll
            for (int m = 0; m < 4; ++m)
                act[m] = *(const float4*)(sh + r * Hn + m * 32 + kc * 4);
            #pragma unroll
            for (int o = 0; o < 4; ++o) {
                const float4* wr = (const float4*)(W1 + (size_t)(jb + o) * (2 * Hn));
                #pragma unroll
                for (int m = 0; m < 4; ++m)
                    p[o] = dot4(__ldg(wr + m * 8 + kc), act[m], p[o]);
            }
            // pass 2: c part (W1 cols 128..255)  [FIX: +Hn floats, not +32]
            #pragma unroll
            for (int m = 0; m < 4; ++m)
                act[m] = *(const float4*)(sc + r * Hn + m * 32 + kc * 4);
            #pragma unroll
            for (int o = 0; o < 4; ++o) {
                const float4* wr = (const float4*)(W1 + (size_t)(jb + o) * (2 * Hn) + Hn);
                #pragma unroll
                for (int m = 0; m < 4; ++m)
                    p[o] = dot4(__ldg(wr + m * 8 + kc), act[m], p[o]);
            }
            float d; int o;
            reduce4(p, kc, d, o);
            if (kc < 4) sa1[r * Hn + jb + o] = tanhf(d + sb1[jb + o]);
        }
        __syncthreads();

        // ===== Phase B: e = W2 @ a1 + b2; 4 outputs/warp (guard j<81) =====
        {
            const int jb = wid * 4;
            if (jb < Dn) {
                float4 act[4];
                #pragma unroll
                for (int m = 0; m < 4; ++m)
                    act[m] = *(const float4*)(sa1 + r * Hn + m * 32 + kc * 4);
                float p[4] = {0.f, 0.f, 0.f, 0.f};
                #pragma unroll
                for (int o = 0; o < 4; ++o) {
                    const int j = jb + o;
                    if (j < Dn) {
                        const float4* wr = (const float4*)(W2 + (size_t)j * Hn);
                        #pragma unroll
                        for (int m = 0; m < 4; ++m)
                            p[o] = dot4(__ldg(wr + m * 8 + kc), act[m], p[o]);
                    }
                }
                float d; int o;
                reduce4(p, kc, d, o);
                const int j = jb + o;
                if (kc < 4 && j < Dn) se[r * DPAD + j] = d + sb2[j];
            }
        }
        __syncthreads();

        // ===== Phase C: softmax over D; write alpha; xw = alpha * x_t =====
        if (tid < 4 * 32) {
            const int cr = tid >> 5;
            const int cl = tid & 31;
            float* er = se + cr * DPAD;
            float v0 = er[cl];
            float v1 = er[cl + 32];
            float v2 = (cl < Dn - 64) ? er[cl + 64] : -3.4e38f;
            float m = fmaxf(fmaxf(v0, v1), v2);
            #pragma unroll
            for (int s = 16; s; s >>= 1) m = fmaxf(m, __shfl_xor_sync(0xffffffffu, m, s));
            float e0 = expf(v0 - m);
            float e1 = expf(v1 - m);
            float e2 = (cl < Dn - 64) ? expf(v2 - m) : 0.0f;
            float ssum = e0 + e1 + e2;
            #pragma unroll
            for (int s = 16; s; s >>= 1) ssum += __shfl_xor_sync(0xffffffffu, ssum, s);
            const float inv = 1.0f / ssum;

            const float* xrow = X + ((size_t)(b0i + cr) * Tn + t) * Dn;
            float* xwr  = sxw + cr * DPAD;
            float* arow = outA + ((size_t)(b0i + cr) * Tn + t) * Dn;

            float a0 = e0 * inv;
            arow[cl] = a0;          xwr[cl]      = a0 * xrow[cl];
            float a1v = e1 * inv;
            arow[cl + 32] = a1v;    xwr[cl + 32] = a1v * xrow[cl + 32];
            if (cl < Dn - 64) {
                float a2 = e2 * inv;
                arow[cl + 64] = a2; xwr[cl + 64] = a2 * xrow[cl + 64];
            }
            if (cl < DPAD - Dn) xwr[Dn + cl] = 0.0f;   // zero pad cols 81..83
        }
        __syncthreads();

        // ===== Phase D: gates = W_ih @ xw + W_hh @ h + bias; 16 outputs/warp =====
        {
            float4 hD[4];
            #pragma unroll
            for (int m = 0; m < 4; ++m)
                hD[m] = *(const float4*)(sh + r * Hn + m * 32 + kc * 4);
            float4 xwD[3];
            xwD[0] = *(const float4*)(sxw + r * DPAD + 0 * 32 + kc * 4);
            xwD[1] = *(const float4*)(sxw + r * DPAD + 1 * 32 + kc * 4);
            xwD[2] = (kc < 5) ? *(const float4*)(sxw + r * DPAD + 2 * 32 + kc * 4)
                              : make_float4(0.f, 0.f, 0.f, 0.f);

            #pragma unroll
            for (int g = 0; g < 4; ++g) {
                const int jb = wid * 16 + g * 4;
                float p[4];
                #pragma unroll
                for (int o = 0; o < 4; ++o) {
                    const int j = jb + o;
                    const float4* wh = (const float4*)(Whh + (size_t)j * Hn);
                    float acc = 0.f;
                    #pragma unroll
                    for (int m = 0; m < 4; ++m)
                        acc = dot4(__ldg(wh + m * 8 + kc), hD[m], acc);
                    const float4* wi = (const float4*)(sWih + j * DPAD);
                    acc = dot4(wi[0 * 8 + kc], xwD[0], acc);
                    acc = dot4(wi[1 * 8 + kc], xwD[1], acc);
                    if (kc < 5)
                        acc = dot4(wi[2 * 8 + kc], xwD[2], acc);
                    p[o] = acc;
                }
                float d; int o;
                reduce4(p, kc, d, o);
                if (kc < 4) sgate[r * Gn + jb + o] = d + sbias[jb + o];
            }
        }
        __syncthreads();

        // ===== Phase E: LSTM cell update, write h out (512 threads) =====
        if (tid < RPB * Hn) {
            const int rr  = tid >> 7;
            const int col = tid & (Hn - 1);
            float gi = sgate[rr * Gn + col];
            float gf = sgate[rr * Gn + Hn + col];
            float gg = sgate[rr * Gn + 2 * Hn + col];
            float go = sgate[rr * Gn + 3 * Hn + col];
            float si = sigmoidf_(gi);
            float sf = sigmoidf_(gf);
            float so = sigmoidf_(go);
            float cn = sf * sc[rr * Hn + col] + si * tanhf(gg);
            float hn = so * tanhf(cn);
            sc[rr * Hn + col] = cn;
            sh[rr * Hn + col] = hn;
            outH[((size_t)(b0i + rr) * Tn + t) * Hn + col] = hn;
        }
        __syncthreads();
    }
}

extern "C" void kernel_launch(void* const* d_in, const int* in_sizes, int n_in,
                              void* d_out, int out_size)
{
    const float* X    = (const float*)d_in[0];
    const float* W1   = (const float*)d_in[1];
    const float* b1   = (const float*)d_in[2];
    const float* W2   = (const float*)d_in[3];
    const float* b2   = (const float*)d_in[4];
    const float* Wih  = (const float*)d_in[5];
    const float* Whh  = (const float*)d_in[6];
    const float* bih  = (const float*)d_in[7];
    const float* bhh  = (const float*)d_in[8];

    float* outH = (float*)d_out;                          // [B, T, H]
    float* outA = outH + (size_t)Bsz * Tn * Hn;           // [B, T, D]

    const size_t smem_bytes = (size_t)SMEM_FLOATS * sizeof(float);
    cudaFuncSetAttribute(encoder_kernel,
                         cudaFuncAttributeMaxDynamicSharedMemorySize,
                         (int)smem_bytes);

    encoder_kernel<<<NBLK, NTH, smem_bytes>>>(
        X, W1, b1, W2, b2, Wih, Whh, bih, bhh, outH, outA);
}

// round 5
// speedup vs baseline: 2.3452x; 1.4322x over previous
#include <cuda_runtime.h>
#include <math.h>

// Problem constants
#define Bsz 512
#define Tn  256
#define Dn  81
#define Hn  128
#define Gn  512            // 4*H
#define RPB 4              // batch rows per block
#define NTH 1024           // threads per block (32 warps)
#define NBLK (Bsz / RPB)   // 128 blocks
#define DPAD 84            // D padded to multiple of 4
#define A1PAD 132          // a1 row stride (conflict-free 4-lane stores)
#define GPAD 516           // gates row stride (conflict-free 4-lane stores)

// Shared memory layout (float offsets; all multiples of 4 -> 16B aligned)
#define OFF_WIH   0                          // [512][84] (cols 81..83 zero)
#define OFF_BIAS  (OFF_WIH + Gn*DPAD)        // [512] b_ih + b_hh
#define OFF_B1    (OFF_BIAS + Gn)            // [128]
#define OFF_B2    (OFF_B1 + Hn)              // [84]
#define OFF_H     (OFF_B2 + DPAD)            // [4][128]
#define OFF_C     (OFF_H + RPB*Hn)           // [4][128]
#define OFF_A1    (OFF_C + RPB*Hn)           // [4][132]
#define OFF_G     (OFF_A1 + RPB*A1PAD)       // [4][516]
#define OFF_XW    (OFF_G + RPB*GPAD)         // [4][84] (cols 81..83 zero)
#define OFF_E     (OFF_XW + RPB*DPAD)        // [4][84]
#define SMEM_FLOATS (OFF_E + RPB*DPAD)

__device__ __forceinline__ float sigmoidf_(float x) {
    return 1.0f / (1.0f + expf(-x));
}

__device__ __forceinline__ float dot4(float4 w, float4 v, float acc) {
    return fmaf(w.x, v.x, fmaf(w.y, v.y, fmaf(w.z, v.z, fmaf(w.w, v.w, acc))));
}

// Reduce 4 per-lane partials (p[r] = partial for batch row r) over ALL 32
// lanes. 6 shfls. Every lane ends with the full sum for row o(lane&3);
// lanes 0..3 cover o = {0,2,1,3} -> store from lane<4.
__device__ __forceinline__ void reduce4_32(const float p[4], int lane,
                                           float& d, int& o) {
    const bool b0 = (lane & 1);
    float q0 = b0 ? p[0] : p[2];
    float q1 = b0 ? p[1] : p[3];
    float v0 = __shfl_xor_sync(0xffffffffu, q0, 1);
    float v1 = __shfl_xor_sync(0xffffffffu, q1, 1);
    float a0 = (b0 ? p[2] : p[0]) + v0;   // rows {0 or 2} pair-sum
    float a1 = (b0 ? p[3] : p[1]) + v1;   // rows {1 or 3} pair-sum
    const bool b1 = (lane & 2);
    float q = b1 ? a0 : a1;
    float v = __shfl_xor_sync(0xffffffffu, q, 2);
    d = (b1 ? a1 : a0) + v;
    d += __shfl_xor_sync(0xffffffffu, d, 4);
    d += __shfl_xor_sync(0xffffffffu, d, 8);
    d += __shfl_xor_sync(0xffffffffu, d, 16);
    o = (b0 ? 2 : 0) | (b1 ? 1 : 0);
}

__global__ __launch_bounds__(NTH, 1)
void encoder_kernel(const float* __restrict__ X,
                    const float* __restrict__ W1,
                    const float* __restrict__ b1,
                    const float* __restrict__ W2,
                    const float* __restrict__ b2,
                    const float* __restrict__ Wih,
                    const float* __restrict__ Whh,
                    const float* __restrict__ bih,
                    const float* __restrict__ bhh,
                    float* __restrict__ outH,
                    float* __restrict__ outA)
{
    extern __shared__ float sm[];
    float* sWih  = sm + OFF_WIH;
    float* sbias = sm + OFF_BIAS;
    float* sb1   = sm + OFF_B1;
    float* sb2   = sm + OFF_B2;
    float* sh    = sm + OFF_H;
    float* sc    = sm + OFF_C;
    float* sa1   = sm + OFF_A1;
    float* sgate = sm + OFF_G;
    float* sxw   = sm + OFF_XW;
    float* se    = sm + OFF_E;

    const int tid  = threadIdx.x;
    const int wid  = tid >> 5;          // 0..31
    const int lane = tid & 31;          // K-chunk owner: floats 4*lane..4*lane+3
    const int b0i  = blockIdx.x * RPB;

    // ---- One-time loads into SMEM ----
    for (int i = tid; i < Gn * DPAD; i += NTH) {
        int row = i / DPAD, col = i - row * DPAD;
        sWih[i] = (col < Dn) ? Wih[row * Dn + col] : 0.0f;
    }
    for (int i = tid; i < Gn; i += NTH) sbias[i] = bih[i] + bhh[i];
    if (tid < Hn)   sb1[tid] = b1[tid];
    if (tid < DPAD) sb2[tid] = (tid < Dn) ? b2[tid] : 0.0f;
    for (int i = tid; i < RPB * Hn; i += NTH) { sh[i] = 0.0f; sc[i] = 0.0f; }
    __syncthreads();

    for (int t = 0; t < Tn; ++t) {
        // ---- Load h,c slices into registers (reused by Phases A and D) ----
        float4 hA[4], cA[4];
        #pragma unroll
        for (int r = 0; r < RPB; ++r) {
            hA[r] = *(const float4*)(sh + r * Hn + 4 * lane);
            cA[r] = *(const float4*)(sc + r * Hn + 4 * lane);
        }

        // ===== Phase A: a1 = tanh(W1 @ [h;c] + b1); 4 j per warp =====
        {
            #pragma unroll
            for (int oi = 0; oi < 4; ++oi) {
                const int j = wid * 4 + oi;
                const float4* w = (const float4*)(W1 + (size_t)j * (2 * Hn));
                float4 wh = __ldg(w + lane);        // dense 512B
                float4 wc = __ldg(w + 32 + lane);   // dense 512B
                float p[4];
                #pragma unroll
                for (int r = 0; r < RPB; ++r)
                    p[r] = dot4(wc, cA[r], dot4(wh, hA[r], 0.0f));
                float d; int o;
                reduce4_32(p, lane, d, o);
                if (lane < 4) sa1[o * A1PAD + j] = tanhf(d + sb1[j]);
            }
        }
        __syncthreads();

        // ===== Phase B: e = W2 @ a1 + b2; 3 j per warp (warps 0..26) =====
        if (wid < 27) {
            float4 aA[4];
            #pragma unroll
            for (int r = 0; r < RPB; ++r)
                aA[r] = *(const float4*)(sa1 + r * A1PAD + 4 * lane);
            #pragma unroll
            for (int oi = 0; oi < 3; ++oi) {
                const int j = wid * 3 + oi;
                float4 w = __ldg((const float4*)(W2 + (size_t)j * Hn) + lane);
                float p[4];
                #pragma unroll
                for (int r = 0; r < RPB; ++r)
                    p[r] = dot4(w, aA[r], 0.0f);
                float d; int o;
                reduce4_32(p, lane, d, o);
                if (lane < 4) se[o * DPAD + j] = d + sb2[j];
            }
        }
        __syncthreads();

        // ===== Phase C: softmax over D; write alpha; xw = alpha * x_t =====
        if (tid < 4 * 32) {
            const int cr = tid >> 5;
            const int cl = tid & 31;
            float* er = se + cr * DPAD;
            float v0 = er[cl];
            float v1 = er[cl + 32];
            float v2 = (cl < Dn - 64) ? er[cl + 64] : -3.4e38f;
            float m = fmaxf(fmaxf(v0, v1), v2);
            #pragma unroll
            for (int s = 16; s; s >>= 1) m = fmaxf(m, __shfl_xor_sync(0xffffffffu, m, s));
            float e0 = expf(v0 - m);
            float e1 = expf(v1 - m);
            float e2 = (cl < Dn - 64) ? expf(v2 - m) : 0.0f;
            float ssum = e0 + e1 + e2;
            #pragma unroll
            for (int s = 16; s; s >>= 1) ssum += __shfl_xor_sync(0xffffffffu, ssum, s);
            const float inv = 1.0f / ssum;

            const float* xrow = X + ((size_t)(b0i + cr) * Tn + t) * Dn;
            float* xwr  = sxw + cr * DPAD;
            float* arow = outA + ((size_t)(b0i + cr) * Tn + t) * Dn;

            float a0 = e0 * inv;
            arow[cl] = a0;          xwr[cl]      = a0 * xrow[cl];
            float a1v = e1 * inv;
            arow[cl + 32] = a1v;    xwr[cl + 32] = a1v * xrow[cl + 32];
            if (cl < Dn - 64) {
                float a2 = e2 * inv;
                arow[cl + 64] = a2; xwr[cl + 64] = a2 * xrow[cl + 64];
            }
            if (cl < DPAD - Dn) xwr[Dn + cl] = 0.0f;   // zero pad cols 81..83
        }
        __syncthreads();

        // ===== Phase D: gates = W_ih @ xw + W_hh @ h + bias; 16 j/warp =====
        {
            const bool act21 = (lane < 21);
            float4 xwA[4];
            #pragma unroll
            for (int r = 0; r < RPB; ++r)
                xwA[r] = act21 ? *(const float4*)(sxw + r * DPAD + 4 * lane)
                               : make_float4(0.f, 0.f, 0.f, 0.f);

            #pragma unroll 4
            for (int oi = 0; oi < 16; ++oi) {
                const int j = wid * 16 + oi;
                float4 wh4 = __ldg((const float4*)(Whh + (size_t)j * Hn) + lane);
                float4 wi4 = act21 ? *(const float4*)(sWih + j * DPAD + 4 * lane)
                                   : make_float4(0.f, 0.f, 0.f, 0.f);
                float p[4];
                #pragma unroll
                for (int r = 0; r < RPB; ++r)
                    p[r] = dot4(wh4, hA[r], dot4(wi4, xwA[r], 0.0f));
                float d; int o;
                reduce4_32(p, lane, d, o);
                if (lane < 4) sgate[o * GPAD + j] = d + sbias[j];
            }
        }
        __syncthreads();

        // ===== Phase E: LSTM cell update, write h out (512 threads) =====
        if (tid < RPB * Hn) {
            const int rr  = tid >> 7;
            const int col = tid & (Hn - 1);
            float gi = sgate[rr * GPAD + col];
            float gf = sgate[rr * GPAD + Hn + col];
            float gg = sgate[rr * GPAD + 2 * Hn + col];
            float go = sgate[rr * GPAD + 3 * Hn + col];
            float si = sigmoidf_(gi);
            float sf = sigmoidf_(gf);
            float so = sigmoidf_(go);
            float cn = sf * sc[rr * Hn + col] + si * tanhf(gg);
            float hn = so * tanhf(cn);
            sc[rr * Hn + col] = cn;
            sh[rr * Hn + col] = hn;
            outH[((size_t)(b0i + rr) * Tn + t) * Hn + col] = hn;
        }
        __syncthreads();
    }
}

extern "C" void kernel_launch(void* const* d_in, const int* in_sizes, int n_in,
                              void* d_out, int out_size)
{
    const float* X    = (const float*)d_in[0];
    const float* W1   = (const float*)d_in[1];
    const float* b1   = (const float*)d_in[2];
    const float* W2   = (const float*)d_in[3];
    const float* b2   = (const float*)d_in[4];
    const float* Wih  = (const float*)d_in[5];
    const float* Whh  = (const float*)d_in[6];
    const float* bih  = (const float*)d_in[7];
    const float* bhh  = (const float*)d_in[8];

    float* outH = (float*)d_out;                          // [B, T, H]
    float* outA = outH + (size_t)Bsz * Tn * Hn;           // [B, T, D]

    const size_t smem_bytes = (size_t)SMEM_FLOATS * sizeof(float);
    cudaFuncSetAttribute(encoder_kernel,
                         cudaFuncAttributeMaxDynamicSharedMemorySize,
                         (int)smem_bytes);

    encoder_kernel<<<NBLK, NTH, smem_bytes>>>(
        X, W1, b1, W2, b2, Wih, Whh, bih, bhh, outH, outA);
}